// round 6
// baseline (speedup 1.0000x reference)
#include <cuda_runtime.h>

// Problem constants (fixed by the reference).
#define NB 4096      // bodies
#define KB 16384     // broad-phase keep count
#define KE 4096      // exact-phase keep count

// Spatial grid: rsum <= 3.0 (radii in [0.5,1.5]); cell 3.25 guarantees any
// AABB-overlapping pair sits in adjacent cells, incl. under edge clamping.
#define NC 128
#define NCELLS (NC * NC)
#define CELL 3.25f
#define ORG  (-208.0f)
#define CAP  64        // per-row gathered candidate cap (fallback: warp brute scan)
#define FULLM 0xffffffffu

#define NBLKS 128      // <= SM count (148) at 1 block/SM => all co-resident
#define TPB   1024     // 128 * 1024 / 32 = 4096 warps = one warp per body

// ---- device scratch (no allocations; all state self-restoring across replays) ----
__device__ int    g_cellCnt[NCELLS];     // zero-init; re-zeroed in phase 1 each run
__device__ int    g_cellStart[NCELLS + 1];
__device__ int    g_cellCur[NCELLS];
__device__ int    g_bodyCell[NB];
__device__ float4 g_sbody[NB];           // cell-sorted (x, y, r, bitcast(idx))
__device__ int    g_cntA[NB];
__device__ int    g_cntP[NB];
__device__ int    g_allowedRow[NB];
__device__ int    g_prefE[NB];
__device__ int    g_prow;
__device__ int    g_winner[NB];          // 0=none, slot+1=i-phase, slot+1+KE=j-phase
__device__ float  g_evx[KE];
__device__ float  g_evy[KE];

// software grid barrier state (generation counter; monotone gen is replay-safe)
__device__ int g_count;
__device__ int g_gen;

__device__ __forceinline__ void gsync() {
    __syncthreads();
    if (threadIdx.x == 0) {
        int my = *(volatile int*)&g_gen;      // read BEFORE arriving
        __threadfence();
        if (atomicAdd(&g_count, 1) == NBLKS - 1) {
            atomicExch(&g_count, 0);
            __threadfence();
            atomicAdd(&g_gen, 1);
        } else {
            while (*(volatile int*)&g_gen == my) __nanosleep(32);
        }
        __threadfence();
    }
    __syncthreads();
}

// Pinned-rounding pair predicate — bit-identical at every use site.
__device__ __forceinline__ void pair_flags(float xi, float yi, float ri,
                                           float xj, float yj, float rj,
                                           bool self, bool& A, bool& P) {
    float dx = fabsf(__fsub_rn(xi, xj));
    float dy = fabsf(__fsub_rn(yi, yj));
    float rs = __fadd_rn(ri, rj);
    A = (dx <= rs) & (dy <= rs) & (!self);
    float d2 = __fadd_rn(__fmaf_rn(dy, dy, __fmul_rn(dx, dx)), 1e-12f);
    P = A & (d2 < __fmul_rn(rs, rs));   // pen>0 <=> rs^2 > d^2+eps (monotone)
}

__device__ __forceinline__ void emit_pair(int slot, int i, int j,
                                          float xi, float yi, float ri,
                                          float xj, float yj, float rj) {
    float dvx = __fsub_rn(xi, xj);
    float dvy = __fsub_rn(yi, yj);
    float rs  = __fadd_rn(ri, rj);
    float d2  = __fadd_rn(__fmaf_rn(dvy, dvy, __fmul_rn(dvx, dvx)), 1e-12f);
    float dist = __fsqrt_rn(d2);
    float s = __fdiv_rn(__fsub_rn(rs, dist), dist);     // pen_depth / dist
    g_evx[slot] = __fmul_rn(dvx, s);
    g_evy[slot] = __fmul_rn(dvy, s);
    atomicMax(&g_winner[i], slot + 1);        // i-phase
    atomicMax(&g_winner[j], slot + 1 + KE);   // j-phase (applied after all i's)
}

// Block-wide exclusive scan over 1024 ints. Contains __syncthreads.
__device__ __forceinline__ int scan1024(int v, int* sh32, int t) {
    int lane = t & 31, w = t >> 5;
    int x = v;
    #pragma unroll
    for (int d = 1; d < 32; d <<= 1) {
        int y = __shfl_up_sync(FULLM, x, d);
        if (lane >= d) x += y;
    }
    if (lane == 31) sh32[w] = x;
    __syncthreads();
    if (w == 0) {
        int s = sh32[lane];
        int acc = s;
        #pragma unroll
        for (int d = 1; d < 32; d <<= 1) {
            int y = __shfl_up_sync(FULLM, acc, d);
            if (lane >= d) acc += y;
        }
        sh32[lane] = acc - s;
    }
    __syncthreads();
    int r = sh32[w] + x - v;
    __syncthreads();
    return r;
}

// 3 contiguous spans of the cell-sorted list around `cell`
struct Spans { int s0, l0, s1, l1, s2, l2, total; };
__device__ __forceinline__ Spans get_spans(int cell) {
    Spans sp;
    int cx = cell & (NC - 1), cy = cell >> 7;
    int cx0 = max(cx - 1, 0), cx1 = min(cx + 1, NC - 1);
    int cy0 = max(cy - 1, 0), cy1 = min(cy + 1, NC - 1);
    sp.s0 = g_cellStart[cy0 * NC + cx0];
    sp.l0 = g_cellStart[cy0 * NC + cx1 + 1] - sp.s0;
    sp.s1 = 0; sp.l1 = 0; sp.s2 = 0; sp.l2 = 0;
    if (cy1 > cy0) {
        sp.s1 = g_cellStart[(cy0 + 1) * NC + cx0];
        sp.l1 = g_cellStart[(cy0 + 1) * NC + cx1 + 1] - sp.s1;
    }
    if (cy1 > cy0 + 1) {
        sp.s2 = g_cellStart[(cy0 + 2) * NC + cx0];
        sp.l2 = g_cellStart[(cy0 + 2) * NC + cx1 + 1] - sp.s2;
    }
    sp.total = sp.l0 + sp.l1 + sp.l2;
    return sp;
}
__device__ __forceinline__ int span_index(const Spans& sp, int c) {
    if (c < sp.l0) return sp.s0 + c;
    c -= sp.l0;
    if (c < sp.l1) return sp.s1 + c;
    return sp.s2 + (c - sp.l1);
}

__global__ void __launch_bounds__(TPB, 1)
k_all(const float* __restrict__ pos, const float* __restrict__ rad,
      float* __restrict__ out) {
    __shared__ int sh32[32];
    __shared__ int shProw, shPc, shAllowedP, shPrefP;
    __shared__ int jls[TPB / 32][CAP];          // 8 KB

    int t    = threadIdx.x;
    int gtid = blockIdx.x * TPB + t;
    const float2* p2 = (const float2*)pos;

    // ---- Phase 0: winner reset + cell assign + histogram ----
    // (g_cellCnt is zero here: static init on first run, re-zeroed in phase 1)
    if (gtid < NB) {
        g_winner[gtid] = 0;
        float2 p = p2[gtid];
        int cx = (int)floorf((p.x - ORG) / CELL);
        int cy = (int)floorf((p.y - ORG) / CELL);
        cx = min(max(cx, 0), NC - 1);
        cy = min(max(cy, 0), NC - 1);
        int c = cy * NC + cx;
        g_bodyCell[gtid] = c;
        atomicAdd(&g_cellCnt[c], 1);
    }
    gsync();

    // ---- Phase 1 (block 0): cell prefix scan (+ re-zero histogram) ----
    if (blockIdx.x == 0) {
        const int CPT = NCELLS / TPB;           // 16
        int cnt[CPT];
        int csum = 0;
        #pragma unroll
        for (int k = 0; k < CPT; k++) {
            cnt[k] = g_cellCnt[t * CPT + k];
            g_cellCnt[t * CPT + k] = 0;         // restore for next replay
            csum += cnt[k];
        }
        int run = scan1024(csum, sh32, t);
        #pragma unroll
        for (int k = 0; k < CPT; k++) {
            g_cellStart[t * CPT + k] = run;
            g_cellCur[t * CPT + k]   = run;
            run += cnt[k];
        }
        if (t == TPB - 1) g_cellStart[NCELLS] = run;   // == NB
    }
    gsync();

    // ---- Phase 2: scatter into cell-sorted list ----
    if (gtid < NB) {
        int c = g_bodyCell[gtid];
        int slot = atomicAdd(&g_cellCur[c], 1);
        float2 p = p2[gtid];
        g_sbody[slot] = make_float4(p.x, p.y, rad[gtid], __int_as_float(gtid));
    }
    gsync();

    // ---- Phase 3: warp-per-body A/P counts ----
    {
        int i = gtid >> 5, lane = gtid & 31;    // exactly NB warps
        float xi = pos[2 * i], yi = pos[2 * i + 1], ri = rad[i];
        Spans sp = get_spans(g_bodyCell[i]);
        int ca = 0, cp = 0;
        for (int base = 0; base < sp.total; base += 32) {
            int c = base + lane;
            bool A = false, P = false;
            if (c < sp.total) {
                float4 b = g_sbody[span_index(sp, c)];
                int j = __float_as_int(b.w);
                pair_flags(xi, yi, ri, b.x, b.y, b.z, j == i, A, P);
            }
            ca += __popc(__ballot_sync(FULLM, A));
            cp += __popc(__ballot_sync(FULLM, P));
        }
        if (lane == 0) { g_cntA[i] = ca; g_cntP[i] = cp; }
    }
    gsync();

    // ---- Phase 4 (block 0): broad prefix + cutoff + exact prefix + partial ----
    if (blockIdx.x == 0) {
        const int BPT = NB / TPB;               // 4 rows/thread, row-major
        int r0 = t * BPT;
        int cA[BPT], cP[BPT];
        int sum = 0;
        #pragma unroll
        for (int m = 0; m < BPT; m++) {
            cA[m] = g_cntA[r0 + m];
            cP[m] = g_cntP[r0 + m];
            sum += cA[m];
        }
        if (t == 0) { shProw = -1; shPc = 0; shAllowedP = 0; }
        int base = scan1024(sum, sh32, t);      // internal syncs publish init

        int pref = base;
        #pragma unroll
        for (int m = 0; m < BPT; m++) {
            int i = r0 + m;
            int a = KB - pref;
            if (a < 0) a = 0;
            if (a > cA[m]) a = cA[m];
            g_allowedRow[i] = a;
            if (pref < KB && pref + cA[m] > KB) { shProw = i; shAllowedP = a; }
            pref += cA[m];
        }
        __syncthreads();

        int prow = shProw;
        int allowedP = shAllowedP;
        unsigned mA = 0, mP = 0;
        int baseA = 0;
        if (prow >= 0) {   // uniform within block 0
            float2 pp = p2[prow];
            float rp = rad[prow];
            #pragma unroll
            for (int m = 0; m < BPT; m++) {
                int j = r0 + m;
                float2 pj = p2[j];
                bool A; bool P;
                pair_flags(pp.x, pp.y, rp, pj.x, pj.y, rad[j], j == prow, A, P);
                mA |= (unsigned)A << m;
                mP |= (unsigned)P << m;
            }
            baseA = scan1024(__popc(mA), sh32, t);
            int cnt = 0;
            #pragma unroll
            for (int m = 0; m < BPT; m++) {
                if ((mP >> m) & 1u) {
                    int ar = baseA + __popc(mA & ((1u << m) - 1u));
                    if (ar < allowedP) cnt++;
                }
            }
            cnt = __reduce_add_sync(FULLM, cnt);
            if ((t & 31) == 0) atomicAdd(&shPc, cnt);
            __syncthreads();
        }
        int pc = (prow >= 0) ? shPc : 0;

        // exact-candidate exclusive prefix per row
        int prefE[BPT];
        {
            int cC[BPT];
            int sumC = 0;
            pref = base;
            #pragma unroll
            for (int m = 0; m < BPT; m++) {
                int c;
                if (pref + cA[m] <= KB)      c = cP[m];
                else if (pref >= KB)         c = 0;
                else                         c = pc;
                cC[m] = c;
                sumC += c;
                pref += cA[m];
            }
            int runC = scan1024(sumC, sh32, t);
            #pragma unroll
            for (int m = 0; m < BPT; m++) {
                prefE[m] = runC;
                g_prefE[r0 + m] = runC;
                runC += cC[m];
            }
            if (prow >= 0 && (prow / BPT) == t) shPrefP = prefE[prow % BPT];
            __syncthreads();
        }
        if (t == 0) g_prow = prow;

        // emit partial row (block-parallel, j-ordered by construction)
        if (prow >= 0) {
            unsigned mC = 0;
            #pragma unroll
            for (int m = 0; m < BPT; m++) {
                if ((mP >> m) & 1u) {
                    int ar = baseA + __popc(mA & ((1u << m) - 1u));
                    if (ar < allowedP) mC |= 1u << m;
                }
            }
            int slotBase = shPrefP + scan1024(__popc(mC), sh32, t);
            float2 pp = p2[prow];
            float rp = rad[prow];
            unsigned mm = mC;
            while (mm) {
                int m = __ffs(mm) - 1;
                mm &= mm - 1;
                int slot = slotBase++;
                if (slot < KE) {
                    int j = r0 + m;
                    float2 pj = p2[j];
                    emit_pair(slot, prow, j, pp.x, pp.y, rp, pj.x, pj.y, rad[j]);
                }
            }
        }
    }
    gsync();

    // ---- Phase 5: warp-per-body ordered emit ----
    {
        int i = gtid >> 5, lane = gtid & 31;
        int wib = t >> 5;
        int prow = g_prow;
        bool active = (i != prow) && (g_allowedRow[i] != 0);
        int baseE = 0, cp = 0;
        if (active) {
            baseE = g_prefE[i];
            cp = g_cntP[i];
            active = (baseE < KE) && (cp != 0);
        }
        if (active) {
            float xi = pos[2 * i], yi = pos[2 * i + 1], ri = rad[i];
            if (cp <= CAP) {
                Spans sp = get_spans(g_bodyCell[i]);
                int k = 0;
                for (int base = 0; base < sp.total; base += 32) {
                    int c = base + lane;
                    bool P = false;
                    int j = -1;
                    if (c < sp.total) {
                        float4 b = g_sbody[span_index(sp, c)];
                        j = __float_as_int(b.w);
                        bool A;
                        pair_flags(xi, yi, ri, b.x, b.y, b.z, j == i, A, P);
                    }
                    unsigned bp = __ballot_sync(FULLM, P);
                    if (P) jls[wib][k + __popc(bp & ((1u << lane) - 1u))] = j;
                    k += __popc(bp);
                }
                __syncwarp();
                if (lane == 0) {    // ascending j -> row-major within-row order
                    for (int a = 1; a < k; a++) {
                        int v = jls[wib][a];
                        int b = a - 1;
                        while (b >= 0 && jls[wib][b] > v) { jls[wib][b + 1] = jls[wib][b]; b--; }
                        jls[wib][b + 1] = v;
                    }
                }
                __syncwarp();
                for (int a = lane; a < k; a += 32) {
                    int slot = baseE + a;
                    if (slot < KE) {
                        int j = jls[wib][a];
                        float xj = pos[2 * j], yj = pos[2 * j + 1];
                        emit_pair(slot, i, j, xi, yi, ri, xj, yj, rad[j]);
                    }
                }
            } else {
                // rare overflow: warp-strided ordered brute scan
                int rank = 0;
                for (int j0 = 0; j0 < NB; j0 += 32) {
                    int j = j0 + lane;
                    float xj = pos[2 * j], yj = pos[2 * j + 1], rj = rad[j];
                    bool A; bool P;
                    pair_flags(xi, yi, ri, xj, yj, rj, j == i, A, P);
                    unsigned bp = __ballot_sync(FULLM, P);
                    if (P) {
                        int slot = baseE + rank + __popc(bp & ((1u << lane) - 1u));
                        if (slot < KE)
                            emit_pair(slot, i, j, xi, yi, ri, xj, yj, rj);
                    }
                    rank += __popc(bp);
                }
            }
        }
    }
    gsync();

    // ---- Phase 6: resolve (last-write-wins via encoded priority) ----
    if (gtid < NB) {
        int i = gtid;
        float x = pos[2 * i];
        float y = pos[2 * i + 1];
        int w = g_winner[i];
        if (w > KE) {                            // j-write wins
            int k = w - KE - 1;
            x = __fsub_rn(x, __fmul_rn(0.5f, g_evx[k]));
            y = __fsub_rn(y, __fmul_rn(0.5f, g_evy[k]));
        } else if (w > 0) {                      // i-write wins
            int k = w - 1;
            x = __fadd_rn(x, __fmul_rn(0.5f, g_evx[k]));
            y = __fadd_rn(y, __fmul_rn(0.5f, g_evy[k]));
        }
        out[2 * i]     = x;
        out[2 * i + 1] = y;
    }
}

extern "C" void kernel_launch(void* const* d_in, const int* in_sizes, int n_in,
                              void* d_out, int out_size) {
    const float* pos;
    const float* rad;
    if (in_sizes[0] == 2 * NB) { pos = (const float*)d_in[0]; rad = (const float*)d_in[1]; }
    else                       { pos = (const float*)d_in[1]; rad = (const float*)d_in[0]; }
    float* out = (float*)d_out;

    k_all<<<NBLKS, TPB>>>(pos, rad, out);
}

// round 7
// speedup vs baseline: 2.0410x; 2.0410x over previous
#include <cuda_runtime.h>

// Problem constants (fixed by the reference).
#define NB 4096      // bodies
#define KB 16384     // broad-phase keep count
#define KE 4096      // exact-phase keep count

// Spatial grid: rsum <= 3.0 (radii in [0.5,1.5]); cell 3.25 guarantees any
// AABB-overlapping pair sits in adjacent cells, incl. under edge clamping.
#define NC 128
#define NCELLS (NC * NC)
#define CELL 3.25f
#define ORG  (-208.0f)
#define CAPC 32        // bucket capacity per cell (peak occupancy ~ Poisson(4.4))
#define CAP  64        // per-row gathered list cap (fallback: warp brute scan)
#define FULLM 0xffffffffu

#define NBLKS 128      // 1 block/SM, <= 148 SMs => all co-resident
#define TPB   1024     // 128*1024/32 = 4096 warps = one warp per body

// ---- device scratch (no allocations; all state self-restoring across replays) ----
__device__ int    g_cellCnt[NCELLS];          // zero-init; re-zeroed in P4
__device__ float4 g_bucket[NCELLS * CAPC];    // (x, y, r, bitcast(idx))
__device__ int2   g_cnt[NB];                  // per-row (cntA, cntP)
__device__ int    g_allowedRow[NB];
__device__ int    g_prefE[NB];
__device__ int    g_prow;
__device__ int    g_winner[NB];               // 0=none; restored by atomicExch in P4
__device__ float  g_evx[KE];
__device__ float  g_evy[KE];

// software grid barrier (generation counter; monotone gen is replay-safe)
__device__ int g_bcount;
__device__ int g_bgen;

__device__ __forceinline__ void gsync() {
    __syncthreads();
    if (threadIdx.x == 0) {
        int my = *(volatile int*)&g_bgen;       // read BEFORE arriving
        __threadfence();
        if (atomicAdd(&g_bcount, 1) == NBLKS - 1) {
            atomicExch(&g_bcount, 0);
            __threadfence();
            atomicAdd(&g_bgen, 1);
        } else {
            while (*(volatile int*)&g_bgen == my) { }   // hard spin (L2 line)
        }
        __threadfence();
    }
    __syncthreads();
}

// Pinned-rounding pair predicate — bit-identical at every use site.
__device__ __forceinline__ void pair_flags(float xi, float yi, float ri,
                                           float xj, float yj, float rj,
                                           bool self, bool& A, bool& P) {
    float dx = fabsf(__fsub_rn(xi, xj));
    float dy = fabsf(__fsub_rn(yi, yj));
    float rs = __fadd_rn(ri, rj);
    A = (dx <= rs) & (dy <= rs) & (!self);
    float d2 = __fadd_rn(__fmaf_rn(dy, dy, __fmul_rn(dx, dx)), 1e-12f);
    P = A & (d2 < __fmul_rn(rs, rs));   // pen>0 <=> rs^2 > d^2+eps (monotone)
}

__device__ __forceinline__ void emit_pair(int slot, int i, int j,
                                          float xi, float yi, float ri,
                                          float xj, float yj, float rj) {
    float dvx = __fsub_rn(xi, xj);
    float dvy = __fsub_rn(yi, yj);
    float rs  = __fadd_rn(ri, rj);
    float d2  = __fadd_rn(__fmaf_rn(dvy, dvy, __fmul_rn(dvx, dvx)), 1e-12f);
    float dist = __fsqrt_rn(d2);
    float s = __fdiv_rn(__fsub_rn(rs, dist), dist);     // pen_depth / dist
    g_evx[slot] = __fmul_rn(dvx, s);
    g_evy[slot] = __fmul_rn(dvy, s);
    atomicMax(&g_winner[i], slot + 1);        // i-phase
    atomicMax(&g_winner[j], slot + 1 + KE);   // j-phase (applied after all i's)
}

// Block-wide exclusive scan over 1024 ints. Contains __syncthreads.
__device__ __forceinline__ int scan1024(int v, int* sh32, int t) {
    int lane = t & 31, w = t >> 5;
    int x = v;
    #pragma unroll
    for (int d = 1; d < 32; d <<= 1) {
        int y = __shfl_up_sync(FULLM, x, d);
        if (lane >= d) x += y;
    }
    if (lane == 31) sh32[w] = x;
    __syncthreads();
    if (w == 0) {
        int s = sh32[lane];
        int acc = s;
        #pragma unroll
        for (int d = 1; d < 32; d <<= 1) {
            int y = __shfl_up_sync(FULLM, acc, d);
            if (lane >= d) acc += y;
        }
        sh32[lane] = acc - s;
    }
    __syncthreads();
    int r = sh32[w] + x - v;
    __syncthreads();
    return r;
}

// warp-collective neighbor candidate setup: 9 cells around (cx,cy).
// After call: st/ct/ce hold (start, count, cell) of the 9 spans in every lane;
// returns total candidate count.
__device__ __forceinline__ int nei_setup(int cx, int cy, int lane,
                                         int* st, int* ct, int* ce) {
    int mycell = -1, mycnt = 0;
    if (lane < 9) {
        int x = cx + (lane % 3) - 1;
        int y = cy + (lane / 3) - 1;
        if (x >= 0 && x < NC && y >= 0 && y < NC) {
            mycell = y * NC + x;
            mycnt = min(g_cellCnt[mycell], CAPC);
        }
    }
    int inc = mycnt;
    #pragma unroll
    for (int d = 1; d < 16; d <<= 1) {
        int y = __shfl_up_sync(FULLM, inc, d);
        if (lane >= d) inc += y;
    }
    int total = __shfl_sync(FULLM, inc, 8);
    int myst = inc - mycnt;
    #pragma unroll
    for (int k = 0; k < 9; k++) {
        st[k] = __shfl_sync(FULLM, myst, k);
        ct[k] = __shfl_sync(FULLM, mycnt, k);
        ce[k] = __shfl_sync(FULLM, mycell, k);
    }
    return total;
}
__device__ __forceinline__ int cand_addr(const int* st, const int* ct,
                                         const int* ce, int c) {
    int bcell = 0, boff = 0;
    #pragma unroll
    for (int k = 0; k < 9; k++)
        if (c >= st[k] && c < st[k] + ct[k]) { bcell = ce[k]; boff = c - st[k]; }
    return bcell * CAPC + boff;
}

__global__ void __launch_bounds__(TPB, 1)
k_all(const float* __restrict__ pos, const float* __restrict__ rad,
      float* __restrict__ out) {
    __shared__ int sh32[32];
    __shared__ int shProw, shPc, shAllowedP, shPrefP;
    __shared__ int jls[TPB / 32][CAP];          // 8 KB

    int t    = threadIdx.x;
    int gtid = blockIdx.x * TPB + t;
    int lane = t & 31;
    int i    = gtid >> 5;                       // body owned by this warp
    const float2* p2 = (const float2*)pos;

    // ---- P0: bucket fill (g_cellCnt is zero here: static init / P4 re-zero) --
    if (gtid < NB) {
        float2 p = p2[gtid];
        int cx = (int)floorf((p.x - ORG) / CELL);
        int cy = (int)floorf((p.y - ORG) / CELL);
        cx = min(max(cx, 0), NC - 1);
        cy = min(max(cy, 0), NC - 1);
        int c = cy * NC + cx;
        int idx = atomicAdd(&g_cellCnt[c], 1);
        if (idx < CAPC)
            g_bucket[c * CAPC + idx] =
                make_float4(p.x, p.y, rad[gtid], __int_as_float(gtid));
    }
    gsync();

    // ---- P1: warp-per-body A/P counts over 9 neighbor buckets ----
    float xi = pos[2 * i], yi = pos[2 * i + 1], ri = rad[i];
    int bcx, bcy;
    {
        bcx = (int)floorf((xi - ORG) / CELL);
        bcy = (int)floorf((yi - ORG) / CELL);
        bcx = min(max(bcx, 0), NC - 1);
        bcy = min(max(bcy, 0), NC - 1);
        int st[9], ct[9], ce[9];
        int total = nei_setup(bcx, bcy, lane, st, ct, ce);
        int ca = 0, cp = 0;
        for (int base = 0; base < total; base += 32) {
            int c = base + lane;
            bool A = false, P = false;
            if (c < total) {
                float4 b = g_bucket[cand_addr(st, ct, ce, c)];
                int j = __float_as_int(b.w);
                pair_flags(xi, yi, ri, b.x, b.y, b.z, j == i, A, P);
            }
            ca += __popc(__ballot_sync(FULLM, A));
            cp += __popc(__ballot_sync(FULLM, P));
        }
        if (lane == 0) g_cnt[i] = make_int2(ca, cp);
    }
    gsync();

    // ---- P2 (block 0): broad prefix + cutoff + exact prefix + partial row ----
    if (blockIdx.x == 0) {
        const int BPT = NB / TPB;               // 4 rows/thread, row-major
        int r0 = t * BPT;
        int cA[BPT], cP[BPT];
        int sum = 0;
        #pragma unroll
        for (int m = 0; m < BPT; m++) {
            int2 c2 = g_cnt[r0 + m];
            cA[m] = c2.x; cP[m] = c2.y;
            sum += cA[m];
        }
        if (t == 0) { shProw = -1; shPc = 0; shAllowedP = 0; }
        int base = scan1024(sum, sh32, t);      // internal syncs publish init

        int pref = base;
        #pragma unroll
        for (int m = 0; m < BPT; m++) {
            int a = KB - pref;
            if (a < 0) a = 0;
            if (a > cA[m]) a = cA[m];
            g_allowedRow[r0 + m] = a;
            if (pref < KB && pref + cA[m] > KB) { shProw = r0 + m; shAllowedP = a; }
            pref += cA[m];
        }
        __syncthreads();

        int prow = shProw;
        int allowedP = shAllowedP;
        unsigned mA = 0, mP = 0;
        int baseA = 0;
        if (prow >= 0) {   // uniform within block 0: brute ordered rescan
            float2 pp = p2[prow];
            float rp = rad[prow];
            #pragma unroll
            for (int m = 0; m < BPT; m++) {
                int j = r0 + m;
                float2 pj = p2[j];
                bool A; bool P;
                pair_flags(pp.x, pp.y, rp, pj.x, pj.y, rad[j], j == prow, A, P);
                mA |= (unsigned)A << m;
                mP |= (unsigned)P << m;
            }
            baseA = scan1024(__popc(mA), sh32, t);
            int cnt = 0;
            #pragma unroll
            for (int m = 0; m < BPT; m++) {
                if ((mP >> m) & 1u) {
                    int ar = baseA + __popc(mA & ((1u << m) - 1u));
                    if (ar < allowedP) cnt++;
                }
            }
            cnt = __reduce_add_sync(FULLM, cnt);
            if ((t & 31) == 0) atomicAdd(&shPc, cnt);
            __syncthreads();
        }
        int pc = (prow >= 0) ? shPc : 0;

        // exact-candidate exclusive prefix per row
        int prefE[BPT];
        {
            int cC[BPT];
            int sumC = 0;
            pref = base;
            #pragma unroll
            for (int m = 0; m < BPT; m++) {
                int c;
                if (pref + cA[m] <= KB)      c = cP[m];
                else if (pref >= KB)         c = 0;
                else                         c = pc;
                cC[m] = c;
                sumC += c;
                pref += cA[m];
            }
            int runC = scan1024(sumC, sh32, t);
            #pragma unroll
            for (int m = 0; m < BPT; m++) {
                prefE[m] = runC;
                g_prefE[r0 + m] = runC;
                runC += cC[m];
            }
            if (prow >= 0 && (prow / BPT) == t) shPrefP = prefE[prow % BPT];
            __syncthreads();
        }
        if (t == 0) g_prow = prow;

        // emit partial row (block-parallel, j-ordered by construction)
        if (prow >= 0) {
            unsigned mC = 0;
            #pragma unroll
            for (int m = 0; m < BPT; m++) {
                if ((mP >> m) & 1u) {
                    int ar = baseA + __popc(mA & ((1u << m) - 1u));
                    if (ar < allowedP) mC |= 1u << m;
                }
            }
            int slotBase = shPrefP + scan1024(__popc(mC), sh32, t);
            float2 pp = p2[prow];
            float rp = rad[prow];
            unsigned mm = mC;
            while (mm) {
                int m = __ffs(mm) - 1;
                mm &= mm - 1;
                int slot = slotBase++;
                if (slot < KE) {
                    int j = r0 + m;
                    float2 pj = p2[j];
                    emit_pair(slot, prow, j, pp.x, pp.y, rp, pj.x, pj.y, rad[j]);
                }
            }
        }
    }
    gsync();

    // ---- P3: warp-per-body ordered emit ----
    {
        int wib = t >> 5;
        int prow = g_prow;
        int allowed = g_allowedRow[i];
        int2 c2 = g_cnt[i];
        int baseE = g_prefE[i];
        bool active = (i != prow) && (allowed != 0) && (baseE < KE) && (c2.y != 0);
        if (active) {
            // non-partial row with allowed > 0  =>  all P-hits kept
            int cp = c2.y;
            if (cp <= CAP) {
                int st[9], ct[9], ce[9];
                int total = nei_setup(bcx, bcy, lane, st, ct, ce);
                int k = 0;
                for (int base = 0; base < total; base += 32) {
                    int c = base + lane;
                    bool P = false;
                    int j = -1;
                    if (c < total) {
                        float4 b = g_bucket[cand_addr(st, ct, ce, c)];
                        j = __float_as_int(b.w);
                        bool A;
                        pair_flags(xi, yi, ri, b.x, b.y, b.z, j == i, A, P);
                    }
                    unsigned bp = __ballot_sync(FULLM, P);
                    if (P) jls[wib][k + __popc(bp & ((1u << lane) - 1u))] = j;
                    k += __popc(bp);
                }
                __syncwarp();
                if (lane == 0) {    // ascending j -> row-major within-row order
                    for (int a = 1; a < k; a++) {
                        int v = jls[wib][a];
                        int b = a - 1;
                        while (b >= 0 && jls[wib][b] > v) {
                            jls[wib][b + 1] = jls[wib][b]; b--;
                        }
                        jls[wib][b + 1] = v;
                    }
                }
                __syncwarp();
                for (int a = lane; a < k; a += 32) {
                    int slot = baseE + a;
                    if (slot < KE) {
                        int j = jls[wib][a];
                        float xj = pos[2 * j], yj = pos[2 * j + 1];
                        emit_pair(slot, i, j, xi, yi, ri, xj, yj, rad[j]);
                    }
                }
            } else {
                // rare overflow: warp-strided ordered brute scan
                int rank = 0;
                for (int j0 = 0; j0 < NB; j0 += 32) {
                    int j = j0 + lane;
                    float xj = pos[2 * j], yj = pos[2 * j + 1], rj = rad[j];
                    bool A; bool P;
                    pair_flags(xi, yi, ri, xj, yj, rj, j == i, A, P);
                    unsigned bp = __ballot_sync(FULLM, P);
                    if (P) {
                        int slot = baseE + rank + __popc(bp & ((1u << lane) - 1u));
                        if (slot < KE)
                            emit_pair(slot, i, j, xi, yi, ri, xj, yj, rj);
                    }
                    rank += __popc(bp);
                }
            }
        }
    }
    gsync();

    // ---- P4: resolve + restore state for next replay ----
    if (gtid < NCELLS) g_cellCnt[gtid] = 0;     // histogram re-zero (post-emit!)
    if (gtid < NB) {
        float x = pos[2 * gtid];
        float y = pos[2 * gtid + 1];
        int w = atomicExch(&g_winner[gtid], 0); // read + restore in one op
        if (w > KE) {                            // j-write wins
            int k = w - KE - 1;
            x = __fsub_rn(x, __fmul_rn(0.5f, g_evx[k]));
            y = __fsub_rn(y, __fmul_rn(0.5f, g_evy[k]));
        } else if (w > 0) {                      // i-write wins
            int k = w - 1;
            x = __fadd_rn(x, __fmul_rn(0.5f, g_evx[k]));
            y = __fadd_rn(y, __fmul_rn(0.5f, g_evy[k]));
        }
        out[2 * gtid]     = x;
        out[2 * gtid + 1] = y;
    }
}

extern "C" void kernel_launch(void* const* d_in, const int* in_sizes, int n_in,
                              void* d_out, int out_size) {
    const float* pos;
    const float* rad;
    if (in_sizes[0] == 2 * NB) { pos = (const float*)d_in[0]; rad = (const float*)d_in[1]; }
    else                       { pos = (const float*)d_in[1]; rad = (const float*)d_in[0]; }
    float* out = (float*)d_out;

    k_all<<<NBLKS, TPB>>>(pos, rad, out);
}

// round 8
// speedup vs baseline: 2.6290x; 1.2881x over previous
#include <cuda_runtime.h>

// Problem constants (fixed by the reference).
#define NB 4096      // bodies
#define KB 16384     // broad-phase keep count
#define KE 4096      // exact-phase keep count

// Spatial grid: rsum <= 3.0 (radii in [0.5,1.5]); cell 3.25 guarantees any
// AABB-overlapping pair sits in adjacent cells, incl. under edge clamping.
#define NC 128
#define NCELLS (NC * NC)
#define CELL 3.25f
#define ORG  (-208.0f)
#define CAPC 32        // bucket capacity per cell (peak occupancy ~ Poisson(4.4))
#define CAP  64        // per-row gathered list cap (fallback: warp brute scan)
#define FULLM 0xffffffffu

#define NBLKS 128      // 1 block/SM => all co-resident; 4096 warps = 1 warp/body
#define TPB   1024
#define NGRP  8        // two-level barrier: 8 groups x 16 blocks

// ---- device scratch (no allocations; all state self-restoring across replays) ----
__device__ int    g_cellCnt[NCELLS];          // zero-init; re-zeroed in P4
__device__ float4 g_bucket[NCELLS * CAPC];    // (x, y, r, bitcast(idx))
__device__ int2   g_cnt[NB];                  // per-row (cntA, cntP)
__device__ int    g_winner[NB];               // 0=none; restored by atomicExch in P4
__device__ float  g_evx[KE];
__device__ float  g_evy[KE];

// two-level monotone barrier state (never reset => replay-safe)
__device__ int g_grp[NGRP * 32];              // stride 32 ints = 128B (no false sharing)
__device__ int g_root;
__device__ int g_gen;

__device__ __forceinline__ void gsync() {
    __syncthreads();
    if (threadIdx.x == 0) {
        int my = *(volatile int*)&g_gen;        // read BEFORE arriving
        __threadfence();
        int v = atomicAdd(&g_grp[(blockIdx.x & (NGRP - 1)) * 32], 1) + 1;
        if ((v & 15) == 0) {                    // 16 blocks per group
            int r = atomicAdd(&g_root, 1) + 1;
            if ((r & (NGRP - 1)) == 0) {
                __threadfence();
                atomicAdd(&g_gen, 1);
            }
        }
        while (*(volatile int*)&g_gen == my) { }
        __threadfence();
    }
    __syncthreads();
}

// Pinned-rounding pair predicate — bit-identical at every use site.
__device__ __forceinline__ void pair_flags(float xi, float yi, float ri,
                                           float xj, float yj, float rj,
                                           bool self, bool& A, bool& P) {
    float dx = fabsf(__fsub_rn(xi, xj));
    float dy = fabsf(__fsub_rn(yi, yj));
    float rs = __fadd_rn(ri, rj);
    A = (dx <= rs) & (dy <= rs) & (!self);
    float d2 = __fadd_rn(__fmaf_rn(dy, dy, __fmul_rn(dx, dx)), 1e-12f);
    P = A & (d2 < __fmul_rn(rs, rs));   // pen>0 <=> rs^2 > d^2+eps (monotone)
}

__device__ __forceinline__ void emit_pair(int slot, int i, int j,
                                          float xi, float yi, float ri,
                                          float xj, float yj, float rj) {
    float dvx = __fsub_rn(xi, xj);
    float dvy = __fsub_rn(yi, yj);
    float rs  = __fadd_rn(ri, rj);
    float d2  = __fadd_rn(__fmaf_rn(dvy, dvy, __fmul_rn(dvx, dvx)), 1e-12f);
    float dist = __fsqrt_rn(d2);
    float s = __fdiv_rn(__fsub_rn(rs, dist), dist);     // pen_depth / dist
    g_evx[slot] = __fmul_rn(dvx, s);
    g_evy[slot] = __fmul_rn(dvy, s);
    atomicMax(&g_winner[i], slot + 1);        // i-phase
    atomicMax(&g_winner[j], slot + 1 + KE);   // j-phase (applied after all i's)
}

// Block-wide exclusive scan over 1024 ints. Contains __syncthreads.
__device__ __forceinline__ int scan1024(int v, int* sh32, int t) {
    int lane = t & 31, w = t >> 5;
    int x = v;
    #pragma unroll
    for (int d = 1; d < 32; d <<= 1) {
        int y = __shfl_up_sync(FULLM, x, d);
        if (lane >= d) x += y;
    }
    if (lane == 31) sh32[w] = x;
    __syncthreads();
    if (w == 0) {
        int s = sh32[lane];
        int acc = s;
        #pragma unroll
        for (int d = 1; d < 32; d <<= 1) {
            int y = __shfl_up_sync(FULLM, acc, d);
            if (lane >= d) acc += y;
        }
        sh32[lane] = acc - s;
    }
    __syncthreads();
    int r = sh32[w] + x - v;
    __syncthreads();
    return r;
}

// warp-collective neighbor candidate setup: 9 cells around (cx,cy).
__device__ __forceinline__ int nei_setup(int cx, int cy, int lane,
                                         int* st, int* ct, int* ce) {
    int mycell = -1, mycnt = 0;
    if (lane < 9) {
        int x = cx + (lane % 3) - 1;
        int y = cy + (lane / 3) - 1;
        if (x >= 0 && x < NC && y >= 0 && y < NC) {
            mycell = y * NC + x;
            mycnt = min(g_cellCnt[mycell], CAPC);
        }
    }
    int inc = mycnt;
    #pragma unroll
    for (int d = 1; d < 16; d <<= 1) {
        int y = __shfl_up_sync(FULLM, inc, d);
        if (lane >= d) inc += y;
    }
    int total = __shfl_sync(FULLM, inc, 8);
    int myst = inc - mycnt;
    #pragma unroll
    for (int k = 0; k < 9; k++) {
        st[k] = __shfl_sync(FULLM, myst, k);
        ct[k] = __shfl_sync(FULLM, mycnt, k);
        ce[k] = __shfl_sync(FULLM, mycell, k);
    }
    return total;
}
__device__ __forceinline__ int cand_addr(const int* st, const int* ct,
                                         const int* ce, int c) {
    int bcell = 0, boff = 0;
    #pragma unroll
    for (int k = 0; k < 9; k++)
        if (c >= st[k] && c < st[k] + ct[k]) { bcell = ce[k]; boff = c - st[k]; }
    return bcell * CAPC + boff;
}

__global__ void __launch_bounds__(TPB, 1)
k_all(const float* __restrict__ pos, const float* __restrict__ rad,
      float* __restrict__ out) {
    __shared__ int sh32[32];
    __shared__ int shProw, shPc, shAllowedP, shPrefP;
    __shared__ int shAllowed[32], shPrefE[32];
    __shared__ int jls[32][CAP];                // 8 KB: per-warp P-hit j-lists

    int t    = threadIdx.x;
    int gtid = blockIdx.x * TPB + t;
    int lane = t & 31;
    int wib  = t >> 5;
    int i    = blockIdx.x * 32 + wib;           // body owned by this warp
    const float2* p2 = (const float2*)pos;

    // ---- P0: bucket fill (g_cellCnt is zero: static init / prior P4 re-zero) --
    if (gtid < NB) {
        float2 p = p2[gtid];
        int cx = (int)floorf((p.x - ORG) / CELL);
        int cy = (int)floorf((p.y - ORG) / CELL);
        cx = min(max(cx, 0), NC - 1);
        cy = min(max(cy, 0), NC - 1);
        int c = cy * NC + cx;
        int idx = atomicAdd(&g_cellCnt[c], 1);
        if (idx < CAPC)
            g_bucket[c * CAPC + idx] =
                make_float4(p.x, p.y, rad[gtid], __int_as_float(gtid));
    }
    gsync();

    // ---- P1: warp-per-body A/P counts + gather P-hit j-list into smem ----
    float xi = pos[2 * i], yi = pos[2 * i + 1], ri = rad[i];
    int cp;                                     // full P count (uniform in warp)
    {
        int bcx = (int)floorf((xi - ORG) / CELL);
        int bcy = (int)floorf((yi - ORG) / CELL);
        bcx = min(max(bcx, 0), NC - 1);
        bcy = min(max(bcy, 0), NC - 1);
        int st[9], ct[9], ce[9];
        int total = nei_setup(bcx, bcy, lane, st, ct, ce);
        int ca = 0, k = 0;
        for (int base = 0; base < total; base += 32) {
            int c = base + lane;
            bool A = false, P = false;
            int j = -1;
            if (c < total) {
                float4 b = g_bucket[cand_addr(st, ct, ce, c)];
                j = __float_as_int(b.w);
                pair_flags(xi, yi, ri, b.x, b.y, b.z, j == i, A, P);
            }
            ca += __popc(__ballot_sync(FULLM, A));
            unsigned bp = __ballot_sync(FULLM, P);
            if (P) {
                int slot = k + __popc(bp & ((1u << lane) - 1u));
                if (slot < CAP) jls[wib][slot] = j;
            }
            k += __popc(bp);
        }
        cp = k;
        if (lane == 0) g_cnt[i] = make_int2(ca, cp);
    }
    gsync();

    // ---- P2 (EVERY block, redundantly): global prefix scans ----
    // Deterministic int math => all blocks compute identical results; each keeps
    // only its own 32 bodies' allowed/prefE in smem. No barrier before P3.
    {
        const int BPT = NB / TPB;               // 4 rows/thread, row-major
        int r0 = t * BPT;
        int blkLo = blockIdx.x * 32, blkHi = blkLo + 32;
        int cA[BPT], cP[BPT];
        int sum = 0;
        #pragma unroll
        for (int m = 0; m < BPT; m++) {
            int2 c2 = g_cnt[r0 + m];
            cA[m] = c2.x; cP[m] = c2.y;
            sum += cA[m];
        }
        if (t == 0) { shProw = -1; shPc = 0; shAllowedP = 0; }
        int base = scan1024(sum, sh32, t);      // internal syncs publish init

        int pref = base;
        #pragma unroll
        for (int m = 0; m < BPT; m++) {
            int row = r0 + m;
            int a = KB - pref;
            if (a < 0) a = 0;
            if (a > cA[m]) a = cA[m];
            if (row >= blkLo && row < blkHi) shAllowed[row - blkLo] = a;
            if (pref < KB && pref + cA[m] > KB) { shProw = row; shAllowedP = a; }
            pref += cA[m];
        }
        __syncthreads();

        int prow = shProw;
        int allowedP = shAllowedP;
        unsigned mA = 0, mP = 0;
        int baseA = 0;
        bool b0 = (blockIdx.x == 0);
        if (prow >= 0 && b0) {   // uniform within block 0: brute ordered rescan
            float2 pp = p2[prow];
            float rp = rad[prow];
            #pragma unroll
            for (int m = 0; m < BPT; m++) {
                int j = r0 + m;
                float2 pj = p2[j];
                bool A; bool P;
                pair_flags(pp.x, pp.y, rp, pj.x, pj.y, rad[j], j == prow, A, P);
                mA |= (unsigned)A << m;
                mP |= (unsigned)P << m;
            }
            baseA = scan1024(__popc(mA), sh32, t);
            int cnt = 0;
            #pragma unroll
            for (int m = 0; m < BPT; m++) {
                if ((mP >> m) & 1u) {
                    int ar = baseA + __popc(mA & ((1u << m) - 1u));
                    if (ar < allowedP) cnt++;
                }
            }
            cnt = __reduce_add_sync(FULLM, cnt);
            if ((t & 31) == 0) atomicAdd(&shPc, cnt);
            __syncthreads();
        } else if (prow >= 0 && !b0) {
            // other blocks must know pc; compute it from the SAME brute rescan
            // (identical math, no emits) — keeps prefixes consistent everywhere
            float2 pp = p2[prow];
            float rp = rad[prow];
            #pragma unroll
            for (int m = 0; m < BPT; m++) {
                int j = r0 + m;
                float2 pj = p2[j];
                bool A; bool P;
                pair_flags(pp.x, pp.y, rp, pj.x, pj.y, rad[j], j == prow, A, P);
                mA |= (unsigned)A << m;
                mP |= (unsigned)P << m;
            }
            baseA = scan1024(__popc(mA), sh32, t);
            int cnt = 0;
            #pragma unroll
            for (int m = 0; m < BPT; m++) {
                if ((mP >> m) & 1u) {
                    int ar = baseA + __popc(mA & ((1u << m) - 1u));
                    if (ar < allowedP) cnt++;
                }
            }
            cnt = __reduce_add_sync(FULLM, cnt);
            if ((t & 31) == 0) atomicAdd(&shPc, cnt);
            __syncthreads();
        }
        int pc = (prow >= 0) ? shPc : 0;

        // exact-candidate exclusive prefix per row
        {
            int cC[BPT];
            int sumC = 0;
            pref = base;
            #pragma unroll
            for (int m = 0; m < BPT; m++) {
                int c;
                if (pref + cA[m] <= KB)      c = cP[m];
                else if (pref >= KB)         c = 0;
                else                         c = pc;
                cC[m] = c;
                sumC += c;
                pref += cA[m];
            }
            int runC = scan1024(sumC, sh32, t);
            #pragma unroll
            for (int m = 0; m < BPT; m++) {
                int row = r0 + m;
                if (row >= blkLo && row < blkHi) shPrefE[row - blkLo] = runC;
                if (prow == row) shPrefP = runC;
                runC += cC[m];
            }
            __syncthreads();
        }

        // block 0 only: emit partial row (block-parallel, j-ordered)
        if (prow >= 0 && b0) {
            unsigned mC = 0;
            #pragma unroll
            for (int m = 0; m < BPT; m++) {
                if ((mP >> m) & 1u) {
                    int ar = baseA + __popc(mA & ((1u << m) - 1u));
                    if (ar < allowedP) mC |= 1u << m;
                }
            }
            int slotBase = shPrefP + scan1024(__popc(mC), sh32, t);
            float2 pp = p2[prow];
            float rp = rad[prow];
            unsigned mm = mC;
            while (mm) {
                int m = __ffs(mm) - 1;
                mm &= mm - 1;
                int slot = slotBase++;
                if (slot < KE) {
                    int j = r0 + m;
                    float2 pj = p2[j];
                    emit_pair(slot, prow, j, pp.x, pp.y, rp, pj.x, pj.y, rad[j]);
                }
            }
        }
    }

    // ---- P3: emit own body from the stored j-list (no barrier needed: all
    // winner writes are commutative atomicMax, ev slots are disjoint) ----
    {
        int prow = shProw;
        int allowed = shAllowed[wib];
        int baseE = shPrefE[wib];
        bool active = (i != prow) && (allowed != 0) && (baseE < KE) && (cp != 0);
        if (active) {
            // non-partial row with allowed > 0  =>  all P-hits kept
            if (cp <= CAP) {
                __syncwarp();
                if (lane == 0) {    // ascending j -> row-major within-row order
                    for (int a = 1; a < cp; a++) {
                        int v = jls[wib][a];
                        int b = a - 1;
                        while (b >= 0 && jls[wib][b] > v) {
                            jls[wib][b + 1] = jls[wib][b]; b--;
                        }
                        jls[wib][b + 1] = v;
                    }
                }
                __syncwarp();
                for (int a = lane; a < cp; a += 32) {
                    int slot = baseE + a;
                    if (slot < KE) {
                        int j = jls[wib][a];
                        float xj = pos[2 * j], yj = pos[2 * j + 1];
                        emit_pair(slot, i, j, xi, yi, ri, xj, yj, rad[j]);
                    }
                }
            } else {
                // rare overflow: warp-strided ordered brute scan
                int rank = 0;
                for (int j0 = 0; j0 < NB; j0 += 32) {
                    int j = j0 + lane;
                    float xj = pos[2 * j], yj = pos[2 * j + 1], rj = rad[j];
                    bool A; bool P;
                    pair_flags(xi, yi, ri, xj, yj, rj, j == i, A, P);
                    unsigned bp = __ballot_sync(FULLM, P);
                    if (P) {
                        int slot = baseE + rank + __popc(bp & ((1u << lane) - 1u));
                        if (slot < KE)
                            emit_pair(slot, i, j, xi, yi, ri, xj, yj, rj);
                    }
                    rank += __popc(bp);
                }
            }
        }
    }
    gsync();

    // ---- P4: resolve + restore state for next replay ----
    if (gtid < NCELLS) g_cellCnt[gtid] = 0;     // histogram re-zero (post-emit!)
    if (gtid < NB) {
        float x = pos[2 * gtid];
        float y = pos[2 * gtid + 1];
        int w = atomicExch(&g_winner[gtid], 0); // read + restore in one op
        if (w > KE) {                            // j-write wins
            int k = w - KE - 1;
            x = __fsub_rn(x, __fmul_rn(0.5f, g_evx[k]));
            y = __fsub_rn(y, __fmul_rn(0.5f, g_evy[k]));
        } else if (w > 0) {                      // i-write wins
            int k = w - 1;
            x = __fadd_rn(x, __fmul_rn(0.5f, g_evx[k]));
            y = __fadd_rn(y, __fmul_rn(0.5f, g_evy[k]));
        }
        out[2 * gtid]     = x;
        out[2 * gtid + 1] = y;
    }
}

extern "C" void kernel_launch(void* const* d_in, const int* in_sizes, int n_in,
                              void* d_out, int out_size) {
    const float* pos;
    const float* rad;
    if (in_sizes[0] == 2 * NB) { pos = (const float*)d_in[0]; rad = (const float*)d_in[1]; }
    else                       { pos = (const float*)d_in[1]; rad = (const float*)d_in[0]; }
    float* out = (float*)d_out;

    k_all<<<NBLKS, TPB>>>(pos, rad, out);
}

// round 9
// speedup vs baseline: 2.9443x; 1.1199x over previous
#include <cuda_runtime.h>

// Problem constants (fixed by the reference).
#define NB 4096      // bodies
#define KB 16384     // broad-phase keep count
#define KE 4096      // exact-phase keep count

// Spatial grid: rsum <= 3.0 (radii in [0.5,1.5]); cell 3.25 guarantees any
// AABB-overlapping pair sits in adjacent cells, incl. under edge clamping.
#define NC 128
#define NCELLS (NC * NC)
#define CELL 3.25f
#define ORG  (-208.0f)
#define CAPC 32        // bucket capacity per cell (peak occupancy ~ Poisson(4.4))
#define CAP  64        // per-row gathered list cap (fallback: warp brute scan)
#define FULLM 0xffffffffu

#define NBLKS 128      // 1 block/SM => co-resident; 4096 warps = 1 warp/body
#define TPB   1024
#define NGRP  8        // two-level barrier: 8 groups x 16 blocks

// ---- device scratch (no allocations; all state self-restoring across replays) ----
__device__ int    g_cellCnt[NCELLS];          // zero-init; re-zeroed in P2
__device__ float4 g_bucket[NCELLS * CAPC];    // (x, y, r, bitcast(idx))
__device__ int2   g_blkSum[NBLKS];            // per-block (sumA, sumP)
__device__ int    g_winner[NB];               // 0=none; restored by atomicExch in P4
__device__ float  g_evx[KE];
__device__ float  g_evy[KE];

// two-level monotone barrier state (never reset => replay-safe)
__device__ int g_grp[NGRP * 32];              // stride 32 ints (no false sharing)
__device__ int g_root;
__device__ int g_gen;

__device__ __forceinline__ void gsync() {
    __syncthreads();
    if (threadIdx.x == 0) {
        int my = *(volatile int*)&g_gen;        // read BEFORE arriving
        __threadfence();
        int v = atomicAdd(&g_grp[(blockIdx.x & (NGRP - 1)) * 32], 1) + 1;
        if ((v & 15) == 0) {                    // 16 blocks per group
            int r = atomicAdd(&g_root, 1) + 1;
            if ((r & (NGRP - 1)) == 0) {
                __threadfence();
                atomicAdd(&g_gen, 1);
            }
        }
        while (*(volatile int*)&g_gen == my) { }
        __threadfence();
    }
    __syncthreads();
}

// Pinned-rounding pair predicate — bit-identical at every use site.
__device__ __forceinline__ void pair_flags(float xi, float yi, float ri,
                                           float xj, float yj, float rj,
                                           bool self, bool& A, bool& P) {
    float dx = fabsf(__fsub_rn(xi, xj));
    float dy = fabsf(__fsub_rn(yi, yj));
    float rs = __fadd_rn(ri, rj);
    A = (dx <= rs) & (dy <= rs) & (!self);
    float d2 = __fadd_rn(__fmaf_rn(dy, dy, __fmul_rn(dx, dx)), 1e-12f);
    P = A & (d2 < __fmul_rn(rs, rs));   // pen>0 <=> rs^2 > d^2+eps (monotone)
}

__device__ __forceinline__ void emit_pair(int slot, int i, int j,
                                          float xi, float yi, float ri,
                                          float xj, float yj, float rj) {
    float dvx = __fsub_rn(xi, xj);
    float dvy = __fsub_rn(yi, yj);
    float rs  = __fadd_rn(ri, rj);
    float d2  = __fadd_rn(__fmaf_rn(dvy, dvy, __fmul_rn(dvx, dvx)), 1e-12f);
    float dist = __fsqrt_rn(d2);
    float s = __fdiv_rn(__fsub_rn(rs, dist), dist);     // pen_depth / dist
    g_evx[slot] = __fmul_rn(dvx, s);
    g_evy[slot] = __fmul_rn(dvy, s);
    atomicMax(&g_winner[i], slot + 1);        // i-phase
    atomicMax(&g_winner[j], slot + 1 + KE);   // j-phase (applied after all i's)
}

// Block-wide exclusive scan over 1024 ints (only used on the rare
// partial-row path). Contains __syncthreads.
__device__ __forceinline__ int scan1024(int v, int* sh32, int t) {
    int lane = t & 31, w = t >> 5;
    int x = v;
    #pragma unroll
    for (int d = 1; d < 32; d <<= 1) {
        int y = __shfl_up_sync(FULLM, x, d);
        if (lane >= d) x += y;
    }
    if (lane == 31) sh32[w] = x;
    __syncthreads();
    if (w == 0) {
        int s = sh32[lane];
        int acc = s;
        #pragma unroll
        for (int d = 1; d < 32; d <<= 1) {
            int y = __shfl_up_sync(FULLM, acc, d);
            if (lane >= d) acc += y;
        }
        sh32[lane] = acc - s;
    }
    __syncthreads();
    int r = sh32[w] + x - v;
    __syncthreads();
    return r;
}

// warp-collective neighbor candidate setup: 9 cells around (cx,cy).
__device__ __forceinline__ int nei_setup(int cx, int cy, int lane,
                                         int* st, int* ct, int* ce) {
    int mycell = -1, mycnt = 0;
    if (lane < 9) {
        int x = cx + (lane % 3) - 1;
        int y = cy + (lane / 3) - 1;
        if (x >= 0 && x < NC && y >= 0 && y < NC) {
            mycell = y * NC + x;
            mycnt = min(g_cellCnt[mycell], CAPC);
        }
    }
    int inc = mycnt;
    #pragma unroll
    for (int d = 1; d < 16; d <<= 1) {
        int y = __shfl_up_sync(FULLM, inc, d);
        if (lane >= d) inc += y;
    }
    int total = __shfl_sync(FULLM, inc, 8);
    int myst = inc - mycnt;
    #pragma unroll
    for (int k = 0; k < 9; k++) {
        st[k] = __shfl_sync(FULLM, myst, k);
        ct[k] = __shfl_sync(FULLM, mycnt, k);
        ce[k] = __shfl_sync(FULLM, mycell, k);
    }
    return total;
}
__device__ __forceinline__ int cand_addr(const int* st, const int* ct,
                                         const int* ce, int c) {
    int bcell = 0, boff = 0;
    #pragma unroll
    for (int k = 0; k < 9; k++)
        if (c >= st[k] && c < st[k] + ct[k]) { bcell = ce[k]; boff = c - st[k]; }
    return bcell * CAPC + boff;
}

__global__ void __launch_bounds__(TPB, 1)
k_all(const float* __restrict__ pos, const float* __restrict__ rad,
      float* __restrict__ out) {
    __shared__ int sh32[32];
    __shared__ int shCA[32], shCP[32];          // per-warp row counts
    __shared__ int shAllowed[32], shPrefE[32];
    __shared__ int shProw, shAllowedP, shPrefP;
    __shared__ int sPA[NBLKS], sPP[NBLKS];      // exclusive block prefixes
    __shared__ int jls[32][CAP];                // 8 KB: per-warp P-hit j-lists

    int t    = threadIdx.x;
    int blk  = blockIdx.x;
    int lane = t & 31;
    int wib  = t >> 5;
    int i    = blk * 32 + wib;                  // body owned by this warp
    const float2* p2 = (const float2*)pos;

    // ---- P0: warp-leader inserts own body into its cell bucket ----
    float xi, yi, ri;
    int cellc;
    {
        float px = 0.f, py = 0.f, pr = 0.f;
        int c = 0;
        if (lane == 0) {
            float2 p = p2[i];
            px = p.x; py = p.y; pr = rad[i];
            int cx = (int)floorf((px - ORG) / CELL);
            int cy = (int)floorf((py - ORG) / CELL);
            cx = min(max(cx, 0), NC - 1);
            cy = min(max(cy, 0), NC - 1);
            c = cy * NC + cx;
            int idx = atomicAdd(&g_cellCnt[c], 1);
            if (idx < CAPC)
                g_bucket[c * CAPC + idx] =
                    make_float4(px, py, pr, __int_as_float(i));
        }
        xi    = __shfl_sync(FULLM, px, 0);
        yi    = __shfl_sync(FULLM, py, 0);
        ri    = __shfl_sync(FULLM, pr, 0);
        cellc = __shfl_sync(FULLM, c, 0);
    }
    gsync();

    // ---- P1: warp-per-body A/P counts + gather P-hit j-list into smem ----
    int cp;                                     // P count (uniform in warp)
    {
        int cx = cellc & (NC - 1), cy = cellc >> 7;
        int st[9], ct[9], ce[9];
        int total = nei_setup(cx, cy, lane, st, ct, ce);
        int ca = 0, k = 0;
        for (int base = 0; base < total; base += 32) {
            int c = base + lane;
            bool A = false, P = false;
            int j = -1;
            if (c < total) {
                float4 b = g_bucket[cand_addr(st, ct, ce, c)];
                j = __float_as_int(b.w);
                pair_flags(xi, yi, ri, b.x, b.y, b.z, j == i, A, P);
            }
            ca += __popc(__ballot_sync(FULLM, A));
            unsigned bp = __ballot_sync(FULLM, P);
            if (P) {
                int slot = k + __popc(bp & ((1u << lane) - 1u));
                if (slot < CAP) jls[wib][slot] = j;
            }
            k += __popc(bp);
        }
        cp = k;
        if (lane == 0) { shCA[wib] = ca; shCP[wib] = cp; }
    }
    __syncthreads();
    if (t == 0) {                               // publish block sums
        int sa = 0, sp = 0;
        #pragma unroll
        for (int w = 0; w < 32; w++) { sa += shCA[w]; sp += shCP[w]; }
        g_blkSum[blk] = make_int2(sa, sp);
        shProw = -1; shAllowedP = 0;
    }
    gsync();

    // ---- P2: hierarchical prefix (128 block sums), cutoff, re-zero cellCnt ----
    // re-zero this block's slice of the cell histogram (last read in P1)
    if (t < NCELLS / NBLKS) g_cellCnt[blk * (NCELLS / NBLKS) + t] = 0;
    // warp 0: scan 128 block sums -> exclusive prefixes in smem
    if (wib == 0) {
        int a0 = 0, a1 = 0, a2 = 0, a3 = 0, p0 = 0, p1 = 0, p2_ = 0, p3 = 0;
        {
            int2 v0 = g_blkSum[4 * lane + 0];
            int2 v1 = g_blkSum[4 * lane + 1];
            int2 v2 = g_blkSum[4 * lane + 2];
            int2 v3 = g_blkSum[4 * lane + 3];
            a0 = v0.x; a1 = v1.x; a2 = v2.x; a3 = v3.x;
            p0 = v0.y; p1 = v1.y; p2_ = v2.y; p3 = v3.y;
        }
        int gA = a0 + a1 + a2 + a3;
        int gP = p0 + p1 + p2_ + p3;
        int xA = gA, xP = gP;
        #pragma unroll
        for (int d = 1; d < 32; d <<= 1) {
            int yA = __shfl_up_sync(FULLM, xA, d);
            int yP = __shfl_up_sync(FULLM, xP, d);
            if (lane >= d) { xA += yA; xP += yP; }
        }
        int baseAex = xA - gA, basePex = xP - gP;
        sPA[4 * lane + 0] = baseAex;
        sPA[4 * lane + 1] = baseAex + a0;
        sPA[4 * lane + 2] = baseAex + a0 + a1;
        sPA[4 * lane + 3] = baseAex + a0 + a1 + a2;
        sPP[4 * lane + 0] = basePex;
        sPP[4 * lane + 1] = basePex + p0;
        sPP[4 * lane + 2] = basePex + p0 + p1;
        sPP[4 * lane + 3] = basePex + p0 + p1 + p2_;
    }
    __syncthreads();
    // warp 0: intra-block row prefixes for this block's 32 rows
    if (wib == 0) {
        int prefA0 = sPA[blk], prefP0 = sPP[blk];
        int ca = shCA[lane], cprow = shCP[lane];
        int xA = ca, xP = cprow;
        #pragma unroll
        for (int d = 1; d < 32; d <<= 1) {
            int yA = __shfl_up_sync(FULLM, xA, d);
            int yP = __shfl_up_sync(FULLM, xP, d);
            if (lane >= d) { xA += yA; xP += yP; }
        }
        int pref  = prefA0 + xA - ca;           // global exclusive A-prefix of row
        int prefE = prefP0 + xP - cprow;        // global exclusive P-prefix of row
        int a = KB - pref;
        if (a < 0) a = 0;
        if (a > ca) a = ca;
        shAllowed[lane] = a;
        shPrefE[lane]   = prefE;
        if (pref < KB && pref + ca > KB) {      // partial row lives in MY block
            shProw = blk * 32 + lane;
            shAllowedP = a;
            shPrefP = prefE;
        }
    }
    __syncthreads();

    // rare: this block owns the broad-cutoff partial row -> ordered brute emit
    if (shProw >= 0) {                          // block-uniform branch
        int prow = shProw;
        int allowedP = shAllowedP;
        float2 pp = p2[prow];
        float rp = rad[prow];
        unsigned mA = 0, mP = 0;
        int r0 = t * 4;
        #pragma unroll
        for (int m = 0; m < 4; m++) {
            int j = r0 + m;
            float2 pj = p2[j];
            bool A; bool P;
            pair_flags(pp.x, pp.y, rp, pj.x, pj.y, rad[j], j == prow, A, P);
            mA |= (unsigned)A << m;
            mP |= (unsigned)P << m;
        }
        int baseA = scan1024(__popc(mA), sh32, t);
        unsigned mC = 0;
        #pragma unroll
        for (int m = 0; m < 4; m++) {
            if ((mP >> m) & 1u) {
                int ar = baseA + __popc(mA & ((1u << m) - 1u));
                if (ar < allowedP) mC |= 1u << m;
            }
        }
        int slotBase = shPrefP + scan1024(__popc(mC), sh32, t);
        unsigned mm = mC;
        while (mm) {
            int m = __ffs(mm) - 1;
            mm &= mm - 1;
            int slot = slotBase++;
            if (slot < KE) {
                int j = r0 + m;
                float2 pj = p2[j];
                emit_pair(slot, prow, j, pp.x, pp.y, rp, pj.x, pj.y, rad[j]);
            }
        }
    }

    // ---- P3: emit own body from stored j-list (winner writes commutative) ----
    {
        int prow = shProw;
        int allowed = shAllowed[wib];
        int baseE = shPrefE[wib];
        bool active = (i != prow) && (allowed != 0) && (baseE < KE) && (cp != 0);
        if (active) {
            // non-partial row with allowed > 0  =>  all P-hits kept
            if (cp <= CAP) {
                if (lane == 0) {    // ascending j -> row-major within-row order
                    for (int a = 1; a < cp; a++) {
                        int v = jls[wib][a];
                        int b = a - 1;
                        while (b >= 0 && jls[wib][b] > v) {
                            jls[wib][b + 1] = jls[wib][b]; b--;
                        }
                        jls[wib][b + 1] = v;
                    }
                }
                __syncwarp();
                for (int a = lane; a < cp; a += 32) {
                    int slot = baseE + a;
                    if (slot < KE) {
                        int j = jls[wib][a];
                        float xj = pos[2 * j], yj = pos[2 * j + 1];
                        emit_pair(slot, i, j, xi, yi, ri, xj, yj, rad[j]);
                    }
                }
            } else {
                // rare overflow: warp-strided ordered brute scan
                int rank = 0;
                for (int j0 = 0; j0 < NB; j0 += 32) {
                    int j = j0 + lane;
                    float xj = pos[2 * j], yj = pos[2 * j + 1], rj = rad[j];
                    bool A; bool P;
                    pair_flags(xi, yi, ri, xj, yj, rj, j == i, A, P);
                    unsigned bp = __ballot_sync(FULLM, P);
                    if (P) {
                        int slot = baseE + rank + __popc(bp & ((1u << lane) - 1u));
                        if (slot < KE)
                            emit_pair(slot, i, j, xi, yi, ri, xj, yj, rj);
                    }
                    rank += __popc(bp);
                }
            }
        }
    }
    gsync();

    // ---- P4: warp-leader resolve (x,y already in registers) + winner restore --
    if (lane == 0) {
        float x = xi, y = yi;
        int w = atomicExch(&g_winner[i], 0);    // read + restore in one op
        if (w > KE) {                            // j-write wins
            int k = w - KE - 1;
            x = __fsub_rn(x, __fmul_rn(0.5f, g_evx[k]));
            y = __fsub_rn(y, __fmul_rn(0.5f, g_evy[k]));
        } else if (w > 0) {                      // i-write wins
            int k = w - 1;
            x = __fadd_rn(x, __fmul_rn(0.5f, g_evx[k]));
            y = __fadd_rn(y, __fmul_rn(0.5f, g_evy[k]));
        }
        out[2 * i]     = x;
        out[2 * i + 1] = y;
    }
}

extern "C" void kernel_launch(void* const* d_in, const int* in_sizes, int n_in,
                              void* d_out, int out_size) {
    const float* pos;
    const float* rad;
    if (in_sizes[0] == 2 * NB) { pos = (const float*)d_in[0]; rad = (const float*)d_in[1]; }
    else                       { pos = (const float*)d_in[1]; rad = (const float*)d_in[0]; }
    float* out = (float*)d_out;

    k_all<<<NBLKS, TPB>>>(pos, rad, out);
}